// round 9
// baseline (speedup 1.0000x reference)
#include <cuda_runtime.h>
#include <cstdint>

#define T_STEPS 12
#define BATCH   64
#define NODE    207
#define HID     16
#define HDIM    6624          // NODE*HID*2
#define IN_DIM  16560         // NODE*HID*5
#define X_DIM   3312          // NODE*HID
#define WSTRIDE 6656          // padded row stride (1664 float4)
#define NB      414           // persistent grid: 414 blocks * 16 rows = 6624
#define ROWS_PB 16
#define SMEM_BYTES (WSTRIDE * 4)   // 26.6 KB (h staging only) -> 3 CTAs/SM

// Scratch (device globals: allocation-free rule)
__device__ float    g_hz[BATCH * HDIM];
__device__ float    g_inpT[IN_DIM * BATCH];
__device__ float    g_pre[BATCH * HDIM];
__device__ float    g_w[(size_t)HDIM * WSTRIDE];    // padded fp32 W_hh (~176 MB)
__device__ unsigned g_bar[2];                       // [0]=count (monotone), [1]=phase

// ---------------------------------------------------------------------------
__global__ __launch_bounds__(256) void kH(const float* __restrict__ W)
{
    const int o = blockIdx.x;
    for (int i = threadIdx.x; i < WSTRIDE; i += 256)
        g_w[(size_t)o * WSTRIDE + i] = (i < HDIM) ? W[(size_t)o * HDIM + i] : 0.f;
}

// ---------------------------------------------------------------------------
// Kernel A: build inpT[:, b] directly (transposed layout).
// ---------------------------------------------------------------------------
__global__ __launch_bounds__(256) void kA(
    const float* __restrict__ hz, const float* __restrict__ sv_t,
    const float* __restrict__ Wf, const float* __restrict__ bf,
    const float* __restrict__ Wg, const float* __restrict__ bg,
    const float* __restrict__ conv_w, float* __restrict__ inpT)
{
    const int blk = blockIdx.x;
    const int b = blk / NODE;
    const int n = blk % NODE;
    const int tid = threadIdx.x;

    __shared__ float sh[HID], sz[HID], sf[HID * 2], sg[HID * HID];

    if (tid < 32) {
        float v = hz[b * HDIM + n * 32 + tid];
        if (tid & 1) sz[tid >> 1] = v;
        else         sh[tid >> 1] = v;
    }
    __syncthreads();

    {
        float acc = bg[tid];
#pragma unroll
        for (int l = 0; l < HID; l++) acc += sz[l] * Wg[l * 256 + tid];
        sg[tid] = tanhf(acc);
    }
    if (tid < 32) {
        float acc = bf[tid];
#pragma unroll
        for (int i = 0; i < HID; i++) acc += sh[i] * Wf[i * 32 + tid];
        sf[tid] = tanhf(acc);
    }
    __syncthreads();

    if (tid < 32) {
        const int i = tid >> 1, c = tid & 1;
        float acc = 0.f;
#pragma unroll
        for (int j = 0; j < HID; j++) acc += sg[i * HID + j] * sf[j * 2 + c];
        const int base = X_DIM + n * 64 + i * 4 + c * 2;
        inpT[(size_t)base * BATCH + b]       = sf[i * 2 + c];
        inpT[(size_t)(base + 1) * BATCH + b] = acc;
    }
    if (tid < HID) {
        float v = sv_t[(b * NODE + n) * 2 + 1];
        inpT[(size_t)(tid * NODE + n) * BATCH + b] = conv_w[tid] * v;
    }
}

// ---------------------------------------------------------------------------
// Kernel B: pre = inp @ W_ih^T + b_ih
// ---------------------------------------------------------------------------
__global__ __launch_bounds__(256) void kB(
    const float* __restrict__ inpT, const float* __restrict__ Wih,
    const float* __restrict__ bih, float* __restrict__ pre)
{
    const int tid = threadIdx.x;
    const int b  = tid & 63;
    const int jg = tid >> 6;
    const int o0 = blockIdx.x * 16 + jg * 4;

    const float* w0 = Wih + (size_t)o0 * IN_DIM;

    float acc[4];
#pragma unroll
    for (int k = 0; k < 4; k++) acc[k] = 0.f;

    for (int i = 0; i < IN_DIM; i += 4) {
        const float x0 = inpT[(size_t)(i    ) * BATCH + b];
        const float x1 = inpT[(size_t)(i + 1) * BATCH + b];
        const float x2 = inpT[(size_t)(i + 2) * BATCH + b];
        const float x3 = inpT[(size_t)(i + 3) * BATCH + b];
#pragma unroll
        for (int k = 0; k < 4; k++) {
            const float4 w = __ldcs(reinterpret_cast<const float4*>(
                                        w0 + (size_t)k * IN_DIM + i));
            acc[k] += w.x * x0 + w.y * x1 + w.z * x2 + w.w * x3;
        }
    }
#pragma unroll
    for (int k = 0; k < 4; k++)
        pre[b * HDIM + o0 + k] = acc[k] + bih[o0 + k];
}

// ---------------------------------------------------------------------------
// Kernel C (persistent, plain fp32 streaming, high occupancy):
// 414 blocks x 256 threads, 3 CTAs/SM (24 warps/SM, occ 37.5%).
// 16 rows/block, 2 rows/warp. Plain float4 LDG, x4 unroll (8 LDG in flight).
// Grid barrier: monotone count g_bar[0], phase g_bar[1], volatile spin.
// ---------------------------------------------------------------------------
extern __shared__ float s_dyn[];

__global__ __launch_bounds__(256, 3) void kC_persist(
    const float* __restrict__ W, const float* __restrict__ pre,
    const float* __restrict__ bhh, float* __restrict__ hz, int t)
{
    float* sh = s_dyn;                 // [0, WSTRIDE) floats
    const int tid  = threadIdx.x;
    const int warp = tid >> 5;
    const int lane = tid & 31;
    const int rbase = blockIdx.x * ROWS_PB + warp * 2;

    const float4* H4 = reinterpret_cast<const float4*>(sh);
    const float4* W0 = reinterpret_cast<const float4*>(W + (size_t)(rbase    ) * WSTRIDE);
    const float4* W1 = reinterpret_cast<const float4*>(W + (size_t)(rbase + 1) * WSTRIDE);

    if (tid < WSTRIDE - HDIM) sh[HDIM + tid] = 0.f;   // zero smem h pad

    for (int step = 0; step < BATCH; step++) {
        float a0 = 0.f, a1 = 0.f;

        if (step > 0) {
            __syncthreads();          // WAR: previous step's readers done
            const float* hp = hz + (size_t)(step - 1) * HDIM;
            for (int i = tid; i < HDIM; i += 256) sh[i] = __ldcg(hp + i);
            __syncthreads();

            // 52 lane-strided f4 iters per row, x4 unroll
#pragma unroll 1
            for (int c = 0; c < 52; c += 4) {
                float4 wa[4], wb[4], hh[4];
#pragma unroll
                for (int j = 0; j < 4; j++) {
                    const int k = (c + j) * 32 + lane;
                    wa[j] = W0[k];
                    wb[j] = W1[k];
                }
#pragma unroll
                for (int j = 0; j < 4; j++) {
                    const int k = (c + j) * 32 + lane;
                    hh[j] = H4[k];
                }
#pragma unroll
                for (int j = 0; j < 4; j++) {
                    a0 += wa[j].x*hh[j].x + wa[j].y*hh[j].y + wa[j].z*hh[j].z + wa[j].w*hh[j].w;
                    a1 += wb[j].x*hh[j].x + wb[j].y*hh[j].y + wb[j].z*hh[j].z + wb[j].w*hh[j].w;
                }
            }
        }

#pragma unroll
        for (int s = 16; s; s >>= 1) {
            a0 += __shfl_xor_sync(0xffffffffu, a0, s);
            a1 += __shfl_xor_sync(0xffffffffu, a1, s);
        }
        if (lane == 0) {
            const float* pre_b = pre + (size_t)step * HDIM;
            float* hout = hz + (size_t)step * HDIM;
            __stcg(hout + rbase    , tanhf(a0 + pre_b[rbase    ] + bhh[rbase    ]));
            __stcg(hout + rbase + 1, tanhf(a1 + pre_b[rbase + 1] + bhh[rbase + 1]));
        }

        // grid barrier
        __threadfence();
        __syncthreads();
        if (tid == 0) {
            const unsigned k = (unsigned)(t * BATCH + step + 1);
            const unsigned old = atomicAdd(&g_bar[0], 1u);
            if (old == k * NB - 1u) {
                atomicExch(&g_bar[1], k);
            } else {
                volatile unsigned* ph = &g_bar[1];
                while (*ph < k) __nanosleep(64);
            }
        }
        __syncthreads();
    }
}

// ---------------------------------------------------------------------------
extern "C" void kernel_launch(void* const* d_in, const int* in_sizes, int n_in,
                              void* d_out, int out_size)
{
    const float* sv    = (const float*)d_in[0];
    const float* init0 = (const float*)d_in[1];
    const float* Wf    = (const float*)d_in[2];
    const float* bf    = (const float*)d_in[3];
    const float* Wg    = (const float*)d_in[4];
    const float* bg    = (const float*)d_in[5];
    const float* cw    = (const float*)d_in[6];
    const float* Wih   = (const float*)d_in[7];
    const float* bih   = (const float*)d_in[8];
    const float* Whh   = (const float*)d_in[9];
    const float* bhh   = (const float*)d_in[10];

    float *hz, *inpT, *pre, *wpad;
    unsigned* bar;
    cudaGetSymbolAddress((void**)&hz,   g_hz);
    cudaGetSymbolAddress((void**)&inpT, g_inpT);
    cudaGetSymbolAddress((void**)&pre,  g_pre);
    cudaGetSymbolAddress((void**)&wpad, g_w);
    cudaGetSymbolAddress((void**)&bar,  g_bar);

    static int smem_set = 0;
    if (!smem_set) {
        cudaFuncSetAttribute(kC_persist,
                             cudaFuncAttributeMaxDynamicSharedMemorySize,
                             SMEM_BYTES);
        smem_set = 1;
    }

    // Launch order: memset, kH, memcpy, kA, kB, kC -> kC is profiled op #5
    cudaMemsetAsync(bar, 0, 2 * sizeof(unsigned));
    kH<<<HDIM, 256>>>(Whh);
    cudaMemcpyAsync(hz, init0, (size_t)BATCH * HDIM * sizeof(float),
                    cudaMemcpyDeviceToDevice);

    for (int t = 0; t < T_STEPS; t++) {
        kA<<<BATCH * NODE, 256>>>(hz, sv + (size_t)t * BATCH * NODE * 2,
                                  Wf, bf, Wg, bg, cw, inpT);
        kB<<<HDIM / 16, 256>>>(inpT, Wih, bih, pre);
        kC_persist<<<NB, 256, SMEM_BYTES>>>(wpad, pre, bhh, hz, t);
    }

    cudaMemcpyAsync(d_out, hz, (size_t)BATCH * HDIM * sizeof(float),
                    cudaMemcpyDeviceToDevice);
}